// round 15
// baseline (speedup 1.0000x reference)
#include <cuda_runtime.h>
#include <cuda_fp16.h>
#include <cstdint>

// Problem constants (fixed by the dataset)
#define NN      100000      // nodes
#define DIN     256         // input feature dim
#define DOUT    32          // output feature dim
#define GTHREADS 256        // 8 warps
#define RPW     16          // rows per warp (m16)
#define RPB     (RPW * 8)   // 128 rows per block
#define NKS     (DIN / 8)   // 32 k-steps of k8
#define CHUNK_COLS 32       // k-columns per pipeline chunk
#define KSPC    4           // k-steps per chunk
#define NCHUNK  (DIN / CHUNK_COLS)   // 8
#define XS_STRIDE 36        // floats per staged row (bank-spread, 16B aligned)
#define XBUF_FLOATS (RPB * XS_STRIDE)            // 4608 floats = 18 KB
#define BFRAG_N (NKS * 4 * 32)                   // 4096 uint2 total
#define BCHUNK_U2 (KSPC * 4 * 32)                // 512 uint2 = 4 KB per chunk
#define XBUF_BYTES (XBUF_FLOATS * 4)
#define BCHUNK_BYTES (BCHUNK_U2 * 8)
#define SMEM_BYTES (2 * (XBUF_BYTES + BCHUNK_BYTES))   // 44 KB

// ---- Device-global scratch (per rules) ----
__device__ __half g_presup_h[(size_t)NN * DOUT];  // 6.4 MB (fp16 pre_sup)
__device__ uint2  g_bfrag[BFRAG_N];               // 32 KB (fragment-ordered)
// Atomic accumulation target. Zero-initialized at module load; the relu pass
// re-zeroes it every launch so every kernel_launch sees it zeroed.
__device__ float  g_accum[(size_t)NN * DOUT];     // 12.8 MB

// ===========================================================================
// GEMM (tf32 mma.sync). B fragments precomputed once to global in fragment
// order; each block cp.asyncs the 4 KB B-slice of chunk c together with the
// X chunk (one commit group per chunk, double-buffered). Smem 44 KB.
// Epilogue converts fp32 accumulators to fp16 (halves scatter gather bytes).
// ===========================================================================
__device__ __forceinline__ uint32_t f2tf32(float f) {
    uint32_t u;
    asm("cvt.rna.tf32.f32 %0, %1;" : "=r"(u) : "f"(f));
    return u;
}

__device__ __forceinline__ void mma_tf32(float4& d,
                                         uint32_t a0, uint32_t a1, uint32_t a2, uint32_t a3,
                                         uint32_t b0, uint32_t b1) {
    asm volatile("mma.sync.aligned.m16n8k8.row.col.f32.tf32.tf32.f32 "
                 "{%0,%1,%2,%3}, {%4,%5,%6,%7}, {%8,%9}, {%0,%1,%2,%3};"
                 : "+f"(d.x), "+f"(d.y), "+f"(d.z), "+f"(d.w)
                 : "r"(a0), "r"(a1), "r"(a2), "r"(a3), "r"(b0), "r"(b1));
}

__device__ __forceinline__ uint32_t smem_u32(const void* p) {
    uint32_t a;
    asm("{ .reg .u64 t; cvta.to.shared.u64 t, %1; cvt.u32.u64 %0, t; }"
        : "=r"(a) : "l"(p));
    return a;
}

__device__ __forceinline__ void cp_async16(uint32_t dst, const void* src, int nbytes) {
    asm volatile("cp.async.ca.shared.global [%0], [%1], 16, %2;"
                 :: "r"(dst), "l"(src), "r"(nbytes) : "memory");
}

// Issue cp.async for one chunk: X tile slice (32 cols x 128 rows) + B slice.
__device__ __forceinline__ void issue_chunk(uint32_t xs_addr, uint32_t bs_addr,
                                            const float* __restrict__ x,
                                            int row0, int cidx, int tid) {
    const int kc = cidx * CHUNK_COLS;
#pragma unroll
    for (int j = 0; j < 4; j++) {
        int i    = tid + j * GTHREADS;
        int r    = i >> 3;
        int seg  = i & 7;
        int grow = row0 + r;
        int gsrc = (grow < NN) ? grow : (NN - 1);
        const float* src = x + (size_t)gsrc * DIN + kc + seg * 4;
        uint32_t dst = xs_addr + (uint32_t)(r * (XS_STRIDE * 4) + seg * 16);
        cp_async16(dst, src, (grow < NN) ? 16 : 0);
    }
    {
        const char* bsrc = (const char*)(g_bfrag + (size_t)cidx * BCHUNK_U2) + tid * 16;
        cp_async16(bs_addr + tid * 16, bsrc, 16);
    }
    asm volatile("cp.async.commit_group;" ::: "memory");
}

// Precompute B fragments once (grid 16 x 256)
__global__ void bfrag_kernel(const float* __restrict__ w) {
    int i = blockIdx.x * 256 + threadIdx.x;
    if (i >= BFRAG_N) return;
    int ks  = i >> 7;
    int rem = i & 127;
    int nb  = rem >> 5;
    int ln  = rem & 31;
    int t = ln & 3, g = ln >> 2;
    float w0 = w[(ks * 8 + t)     * DOUT + nb * 8 + g];
    float w1 = w[(ks * 8 + t + 4) * DOUT + nb * 8 + g];
    g_bfrag[i] = make_uint2(f2tf32(w0), f2tf32(w1));
}

__global__ __launch_bounds__(GTHREADS, 4) void gemm_kernel(const float* __restrict__ x) {
    extern __shared__ char smem[];
    float* Xbuf = (float*)smem;
    uint2* Bbuf = (uint2*)(smem + 2 * XBUF_BYTES);
    const uint32_t xb_addr0 = smem_u32(Xbuf);
    const uint32_t xb_addr1 = xb_addr0 + XBUF_BYTES;
    const uint32_t bb_addr0 = smem_u32(Bbuf);
    const uint32_t bb_addr1 = bb_addr0 + BCHUNK_BYTES;

    const int tid  = threadIdx.x;
    const int row0 = blockIdx.x * RPB;

    issue_chunk(xb_addr0, bb_addr0, x, row0, 0, tid);
    issue_chunk(xb_addr1, bb_addr1, x, row0, 1, tid);

    const int wid  = tid >> 5;
    const int lane = tid & 31;
    const int t    = lane & 3;
    const int g    = lane >> 2;
    const int rl   = wid * RPW;

    float4 acc[4];
#pragma unroll
    for (int nb = 0; nb < 4; nb++) acc[nb] = make_float4(0.f, 0.f, 0.f, 0.f);

    const int offA = (rl + g) * XS_STRIDE + t;
    const int offB = (rl + g + 8) * XS_STRIDE + t;

#pragma unroll
    for (int c = 0; c < NCHUNK; c++) {
        if (c < NCHUNK - 1)
            asm volatile("cp.async.wait_group 1;" ::: "memory");
        else
            asm volatile("cp.async.wait_group 0;" ::: "memory");
        __syncthreads();

        const float* Xs = Xbuf + (c & 1) * XBUF_FLOATS;
        const uint2* Bs = Bbuf + (c & 1) * BCHUNK_U2;
#pragma unroll
        for (int ksl = 0; ksl < KSPC; ksl++) {
            const int k0 = ksl * 8;
            uint32_t a0 = f2tf32(Xs[offA + k0]);
            uint32_t a1 = f2tf32(Xs[offB + k0]);
            uint32_t a2 = f2tf32(Xs[offA + k0 + 4]);
            uint32_t a3 = f2tf32(Xs[offB + k0 + 4]);

            const uint2* bp = Bs + ksl * 4 * 32 + lane;
            uint2 b0 = bp[0 * 32];
            uint2 b1 = bp[1 * 32];
            uint2 b2 = bp[2 * 32];
            uint2 b3 = bp[3 * 32];
            mma_tf32(acc[0], a0, a1, a2, a3, b0.x, b0.y);
            mma_tf32(acc[1], a0, a1, a2, a3, b1.x, b1.y);
            mma_tf32(acc[2], a0, a1, a2, a3, b2.x, b2.y);
            mma_tf32(acc[3], a0, a1, a2, a3, b3.x, b3.y);
        }

        if (c + 2 < NCHUNK) {
            __syncthreads();
            issue_chunk((c & 1) ? xb_addr1 : xb_addr0,
                        (c & 1) ? bb_addr1 : bb_addr0,
                        x, row0, c + 2, tid);
        }
    }

    // Epilogue: fp32 -> fp16, one __half2 (4B) store per (row, nb)
    const int r0 = row0 + rl + g;
    const int r1 = row0 + rl + g + 8;
#pragma unroll
    for (int nb = 0; nb < 4; nb++) {
        if (r0 < NN)
            *(__half2*)(g_presup_h + (size_t)r0 * DOUT + nb * 8 + 2 * t) =
                __floats2half2_rn(acc[nb].x, acc[nb].y);
        if (r1 < NN)
            *(__half2*)(g_presup_h + (size_t)r1 * DOUT + nb * 8 + 2 * t) =
                __floats2half2_rn(acc[nb].z, acc[nb].w);
    }
}

// ===========================================================================
// Scatter SpMM  g_accum[row[e]] += val[e] * pre_sup[col[e]]
// 8 threads per edge; each gathers 4 fp16 cols (LDG.64, lane-contiguous
// 64B/edge), converts to fp32, one red.global.add.v4.f32.
// ===========================================================================
__global__ __launch_bounds__(256) void scatter_kernel(const int*   __restrict__ arow,
                                                      const int*   __restrict__ acol,
                                                      const float* __restrict__ aval,
                                                      int n_edges) {
    long long gdx = (long long)blockIdx.x * blockDim.x + threadIdx.x;
    int e    = (int)(gdx >> 3);
    int part = (int)(gdx & 7);
    if (e >= n_edges) return;

    int   r = arow[e];
    int   c = acol[e];
    float v = aval[e];

    // 4 fp16 values = 8 bytes
    uint2 raw = *(const uint2*)(g_presup_h + (size_t)c * DOUT + part * 4);
    float2 f0 = __half22float2(*(__half2*)&raw.x);
    float2 f1 = __half22float2(*(__half2*)&raw.y);
    float m0 = v * f0.x, m1 = v * f0.y, m2 = v * f1.x, m3 = v * f1.y;

    float* dst = g_accum + (size_t)r * DOUT + part * 4;
    asm volatile("red.global.add.v4.f32 [%0], {%1, %2, %3, %4};"
                 :: "l"(dst), "f"(m0), "f"(m1), "f"(m2), "f"(m3)
                 : "memory");
}

// ===========================================================================
// ReLU: out = relu(g_accum); g_accum = 0 (restores invariant for next launch)
// ===========================================================================
__global__ __launch_bounds__(256) void relu_kernel(float* __restrict__ out, int n4) {
    int i = blockIdx.x * 256 + threadIdx.x;
    if (i < n4) {
        float4 v = ((const float4*)g_accum)[i];
        v.x = fmaxf(v.x, 0.f);
        v.y = fmaxf(v.y, 0.f);
        v.z = fmaxf(v.z, 0.f);
        v.w = fmaxf(v.w, 0.f);
        ((float4*)out)[i] = v;
        ((float4*)g_accum)[i] = make_float4(0.f, 0.f, 0.f, 0.f);
    }
}

// ===========================================================================
// kernel_launch: bfrag -> gemm -> scatter -> relu
// ===========================================================================
extern "C" void kernel_launch(void* const* d_in, const int* in_sizes, int n_in,
                              void* d_out, int out_size) {
    const float* x    = (const float*)d_in[0];
    const int*   arow = (const int*)  d_in[1];
    const int*   acol = (const int*)  d_in[2];
    const float* aval = (const float*)d_in[3];
    const float* w    = (const float*)d_in[4];
    float*       out  = (float*)d_out;

    const int n_edges = in_sizes[1];

    cudaFuncSetAttribute(gemm_kernel, cudaFuncAttributeMaxDynamicSharedMemorySize,
                         SMEM_BYTES);

    bfrag_kernel<<<(BFRAG_N + 255) / 256, 256>>>(w);

    gemm_kernel<<<(NN + RPB - 1) / RPB, GTHREADS, SMEM_BYTES>>>(x);

    long long sthreads = (long long)n_edges * 8;
    int sblocks = (int)((sthreads + 255) / 256);
    scatter_kernel<<<sblocks, 256>>>(arow, acol, aval, n_edges);

    int n4 = out_size / 4;
    relu_kernel<<<(n4 + 255) / 256, 256>>>(out, n4);
}

// round 16
// speedup vs baseline: 1.0049x; 1.0049x over previous
#include <cuda_runtime.h>
#include <cstdint>

// Problem constants (fixed by the dataset)
#define NN      100000      // nodes
#define DIN     256         // input feature dim
#define DOUT    32          // output feature dim
#define GTHREADS 256        // 8 warps
#define RPW     16          // rows per warp (m16)
#define RPB     (RPW * 8)   // 128 rows per block
#define NKS     (DIN / 8)   // 32 k-steps of k8
#define CHUNK_COLS 32       // k-columns per pipeline chunk
#define KSPC    4           // k-steps per chunk
#define NCHUNK  (DIN / CHUNK_COLS)   // 8
#define NBUF    3           // pipeline depth
#define XS_STRIDE 36        // floats per staged row (bank-spread, 16B aligned)
#define XBUF_FLOATS (RPB * XS_STRIDE)            // 4608 floats = 18 KB
#define BFRAG_N (NKS * 4 * 32)                   // 4096 uint2 total
#define BCHUNK_U2 (KSPC * 4 * 32)                // 512 uint2 = 4 KB per chunk
#define XBUF_BYTES (XBUF_FLOATS * 4)
#define BCHUNK_BYTES (BCHUNK_U2 * 8)
#define SMEM_BYTES (NBUF * (XBUF_BYTES + BCHUNK_BYTES))   // 66 KB

// ---- Device-global scratch (per rules) ----
__device__ float g_presup[(size_t)NN * DOUT];   // 12.8 MB (fp32 pre_sup)
__device__ uint2 g_bfrag[BFRAG_N];              // 32 KB (fragment-ordered)
// Atomic accumulation target. Zero-initialized at module load; the relu pass
// re-zeroes it every launch so every kernel_launch sees it zeroed.
__device__ float g_accum[(size_t)NN * DOUT];    // 12.8 MB

// ===========================================================================
// GEMM (tf32 mma.sync). B fragments precomputed once to global in fragment
// order; each block cp.asyncs the 4 KB B-slice of chunk c together with the
// X chunk. 3-stage pipeline (wait_group 2): two chunks of prefetch slack.
// Smem 66 KB -> 3 blocks/SM.
// ===========================================================================
__device__ __forceinline__ uint32_t f2tf32(float f) {
    uint32_t u;
    asm("cvt.rna.tf32.f32 %0, %1;" : "=r"(u) : "f"(f));
    return u;
}

__device__ __forceinline__ void mma_tf32(float4& d,
                                         uint32_t a0, uint32_t a1, uint32_t a2, uint32_t a3,
                                         uint32_t b0, uint32_t b1) {
    asm volatile("mma.sync.aligned.m16n8k8.row.col.f32.tf32.tf32.f32 "
                 "{%0,%1,%2,%3}, {%4,%5,%6,%7}, {%8,%9}, {%0,%1,%2,%3};"
                 : "+f"(d.x), "+f"(d.y), "+f"(d.z), "+f"(d.w)
                 : "r"(a0), "r"(a1), "r"(a2), "r"(a3), "r"(b0), "r"(b1));
}

__device__ __forceinline__ uint32_t smem_u32(const void* p) {
    uint32_t a;
    asm("{ .reg .u64 t; cvta.to.shared.u64 t, %1; cvt.u32.u64 %0, t; }"
        : "=r"(a) : "l"(p));
    return a;
}

__device__ __forceinline__ void cp_async16(uint32_t dst, const void* src, int nbytes) {
    asm volatile("cp.async.ca.shared.global [%0], [%1], 16, %2;"
                 :: "r"(dst), "l"(src), "r"(nbytes) : "memory");
}

// Issue cp.async for one chunk: X tile slice (32 cols x 128 rows) + B slice.
__device__ __forceinline__ void issue_chunk(uint32_t xs_addr, uint32_t bs_addr,
                                            const float* __restrict__ x,
                                            int row0, int cidx, int tid) {
    const int kc = cidx * CHUNK_COLS;
#pragma unroll
    for (int j = 0; j < 4; j++) {
        int i    = tid + j * GTHREADS;
        int r    = i >> 3;
        int seg  = i & 7;
        int grow = row0 + r;
        int gsrc = (grow < NN) ? grow : (NN - 1);
        const float* src = x + (size_t)gsrc * DIN + kc + seg * 4;
        uint32_t dst = xs_addr + (uint32_t)(r * (XS_STRIDE * 4) + seg * 16);
        cp_async16(dst, src, (grow < NN) ? 16 : 0);
    }
    {
        const char* bsrc = (const char*)(g_bfrag + (size_t)cidx * BCHUNK_U2) + tid * 16;
        cp_async16(bs_addr + tid * 16, bsrc, 16);
    }
    asm volatile("cp.async.commit_group;" ::: "memory");
}

// Precompute B fragments once (grid 16 x 256)
__global__ void bfrag_kernel(const float* __restrict__ w) {
    int i = blockIdx.x * 256 + threadIdx.x;
    if (i >= BFRAG_N) return;
    int ks  = i >> 7;
    int rem = i & 127;
    int nb  = rem >> 5;
    int ln  = rem & 31;
    int t = ln & 3, g = ln >> 2;
    float w0 = w[(ks * 8 + t)     * DOUT + nb * 8 + g];
    float w1 = w[(ks * 8 + t + 4) * DOUT + nb * 8 + g];
    g_bfrag[i] = make_uint2(f2tf32(w0), f2tf32(w1));
}

__global__ __launch_bounds__(GTHREADS, 3) void gemm_kernel(const float* __restrict__ x) {
    extern __shared__ char smem[];
    // Layout: Xbuf[0..2] | Bbuf[0..2]
    float* Xbuf = (float*)smem;
    uint2* Bbuf = (uint2*)(smem + NBUF * XBUF_BYTES);
    uint32_t xb_addr[NBUF], bb_addr[NBUF];
    const uint32_t xb0 = smem_u32(Xbuf);
    const uint32_t bb0 = smem_u32(Bbuf);
#pragma unroll
    for (int b = 0; b < NBUF; b++) {
        xb_addr[b] = xb0 + b * XBUF_BYTES;
        bb_addr[b] = bb0 + b * BCHUNK_BYTES;
    }

    const int tid  = threadIdx.x;
    const int row0 = blockIdx.x * RPB;

    issue_chunk(xb_addr[0], bb_addr[0], x, row0, 0, tid);
    issue_chunk(xb_addr[1], bb_addr[1], x, row0, 1, tid);
    issue_chunk(xb_addr[2], bb_addr[2], x, row0, 2, tid);

    const int wid  = tid >> 5;
    const int lane = tid & 31;
    const int t    = lane & 3;
    const int g    = lane >> 2;
    const int rl   = wid * RPW;

    float4 acc[4];
#pragma unroll
    for (int nb = 0; nb < 4; nb++) acc[nb] = make_float4(0.f, 0.f, 0.f, 0.f);

    const int offA = (rl + g) * XS_STRIDE + t;
    const int offB = (rl + g + 8) * XS_STRIDE + t;

#pragma unroll
    for (int c = 0; c < NCHUNK; c++) {
        // groups issued so far = min(c+3, NCHUNK); need chunk c complete.
        if (c < NCHUNK - 2)
            asm volatile("cp.async.wait_group 2;" ::: "memory");
        else if (c == NCHUNK - 2)
            asm volatile("cp.async.wait_group 1;" ::: "memory");
        else
            asm volatile("cp.async.wait_group 0;" ::: "memory");
        __syncthreads();

        const int buf = c % NBUF;
        const float* Xs = Xbuf + buf * XBUF_FLOATS;
        const uint2* Bs = Bbuf + buf * BCHUNK_U2;
#pragma unroll
        for (int ksl = 0; ksl < KSPC; ksl++) {
            const int k0 = ksl * 8;
            uint32_t a0 = f2tf32(Xs[offA + k0]);
            uint32_t a1 = f2tf32(Xs[offB + k0]);
            uint32_t a2 = f2tf32(Xs[offA + k0 + 4]);
            uint32_t a3 = f2tf32(Xs[offB + k0 + 4]);

            const uint2* bp = Bs + ksl * 4 * 32 + lane;
            uint2 b0 = bp[0 * 32];
            uint2 b1 = bp[1 * 32];
            uint2 b2 = bp[2 * 32];
            uint2 b3 = bp[3 * 32];
            mma_tf32(acc[0], a0, a1, a2, a3, b0.x, b0.y);
            mma_tf32(acc[1], a0, a1, a2, a3, b1.x, b1.y);
            mma_tf32(acc[2], a0, a1, a2, a3, b2.x, b2.y);
            mma_tf32(acc[3], a0, a1, a2, a3, b3.x, b3.y);
        }

        if (c + NBUF < NCHUNK) {
            __syncthreads();       // all readers of this buffer are done
            issue_chunk(xb_addr[buf], bb_addr[buf], x, row0, c + NBUF, tid);
        }
    }

    // Epilogue: proven float2 stores per (row, nb)
    const int r0 = row0 + rl + g;
    const int r1 = row0 + rl + g + 8;
#pragma unroll
    for (int nb = 0; nb < 4; nb++) {
        if (r0 < NN)
            *(float2*)(g_presup + (size_t)r0 * DOUT + nb * 8 + 2 * t) =
                make_float2(acc[nb].x, acc[nb].y);
        if (r1 < NN)
            *(float2*)(g_presup + (size_t)r1 * DOUT + nb * 8 + 2 * t) =
                make_float2(acc[nb].z, acc[nb].w);
    }
}

// ===========================================================================
// Scatter SpMM  g_accum[row[e]] += val[e] * pre_sup[col[e]]
// Proven Round-8/14 shape: 8 threads per edge (lane-level coalescing),
// one float4 gather + one red.global.add.v4.f32 per thread.
// ===========================================================================
__global__ __launch_bounds__(256) void scatter_kernel(const int*   __restrict__ arow,
                                                      const int*   __restrict__ acol,
                                                      const float* __restrict__ aval,
                                                      int n_edges) {
    long long gdx = (long long)blockIdx.x * blockDim.x + threadIdx.x;
    int e    = (int)(gdx >> 3);
    int part = (int)(gdx & 7);
    if (e >= n_edges) return;

    int   r = arow[e];
    int   c = acol[e];
    float v = aval[e];

    float4 p = *(const float4*)(g_presup + (size_t)c * DOUT + part * 4);
    float m0 = v * p.x, m1 = v * p.y, m2 = v * p.z, m3 = v * p.w;

    float* dst = g_accum + (size_t)r * DOUT + part * 4;
    asm volatile("red.global.add.v4.f32 [%0], {%1, %2, %3, %4};"
                 :: "l"(dst), "f"(m0), "f"(m1), "f"(m2), "f"(m3)
                 : "memory");
}

// ===========================================================================
// ReLU: out = relu(g_accum); g_accum = 0 (restores invariant for next launch)
// ===========================================================================
__global__ __launch_bounds__(256) void relu_kernel(float* __restrict__ out, int n4) {
    int i = blockIdx.x * 256 + threadIdx.x;
    if (i < n4) {
        float4 v = ((const float4*)g_accum)[i];
        v.x = fmaxf(v.x, 0.f);
        v.y = fmaxf(v.y, 0.f);
        v.z = fmaxf(v.z, 0.f);
        v.w = fmaxf(v.w, 0.f);
        ((float4*)out)[i] = v;
        ((float4*)g_accum)[i] = make_float4(0.f, 0.f, 0.f, 0.f);
    }
}

// ===========================================================================
// kernel_launch: bfrag -> gemm -> scatter -> relu
// ===========================================================================
extern "C" void kernel_launch(void* const* d_in, const int* in_sizes, int n_in,
                              void* d_out, int out_size) {
    const float* x    = (const float*)d_in[0];
    const int*   arow = (const int*)  d_in[1];
    const int*   acol = (const int*)  d_in[2];
    const float* aval = (const float*)d_in[3];
    const float* w    = (const float*)d_in[4];
    float*       out  = (float*)d_out;

    const int n_edges = in_sizes[1];

    cudaFuncSetAttribute(gemm_kernel, cudaFuncAttributeMaxDynamicSharedMemorySize,
                         SMEM_BYTES);

    bfrag_kernel<<<(BFRAG_N + 255) / 256, 256>>>(w);

    gemm_kernel<<<(NN + RPB - 1) / RPB, GTHREADS, SMEM_BYTES>>>(x);

    long long sthreads = (long long)n_edges * 8;
    int sblocks = (int)((sthreads + 255) / 256);
    scatter_kernel<<<sblocks, 256>>>(arow, acol, aval, n_edges);

    int n4 = out_size / 4;
    relu_kernel<<<(n4 + 255) / 256, 256>>>(out, n4);
}

// round 17
// speedup vs baseline: 1.0884x; 1.0831x over previous
#include <cuda_runtime.h>
#include <cstdint>

// Problem constants (fixed by the dataset)
#define NN      100000      // nodes
#define DIN     256         // input feature dim
#define DOUT    32          // output feature dim
#define GTHREADS 256        // 8 warps
#define RPW     16          // rows per warp (m16)
#define RPB     (RPW * 8)   // 128 rows per block
#define NKS     (DIN / 8)   // 32 k-steps of k8
#define CHUNK_COLS 32       // k-columns per pipeline chunk
#define KSPC    4           // k-steps per chunk
#define NCHUNK  (DIN / CHUNK_COLS)   // 8
#define XS_STRIDE 36        // floats per staged row (bank-spread, 16B aligned)
#define XBUF_FLOATS (RPB * XS_STRIDE)            // 4608 floats = 18 KB
#define BFRAG_N (NKS * 4 * 32)                   // 4096 uint2 total
#define BCHUNK_U2 (KSPC * 4 * 32)                // 512 uint2 = 4 KB per chunk
#define XBUF_BYTES (XBUF_FLOATS * 4)
#define BCHUNK_BYTES (BCHUNK_U2 * 8)
#define SMEM_BYTES (2 * (XBUF_BYTES + BCHUNK_BYTES))   // 44 KB

// ---- Device-global scratch (per rules) ----
__device__ float g_presup[(size_t)NN * DOUT];   // 12.8 MB (fp32 pre_sup)
__device__ uint2 g_bfrag[BFRAG_N];              // 32 KB (fragment-ordered)
// Atomic accumulation target. Zero-initialized at module load; the relu pass
// re-zeroes it every launch so every kernel_launch sees it zeroed.
__device__ float g_accum[(size_t)NN * DOUT];    // 12.8 MB

// ===========================================================================
// GEMM (tf32 mma.sync): measured-best R13/R14 configuration.
// B fragments precomputed once to global in fragment order; each block
// cp.asyncs the 4 KB B-slice of chunk c together with the X chunk (one
// commit group per chunk, double-buffered). Smem 44 KB -> 4 blocks/SM.
// ===========================================================================
__device__ __forceinline__ uint32_t f2tf32(float f) {
    uint32_t u;
    asm("cvt.rna.tf32.f32 %0, %1;" : "=r"(u) : "f"(f));
    return u;
}

__device__ __forceinline__ void mma_tf32(float4& d,
                                         uint32_t a0, uint32_t a1, uint32_t a2, uint32_t a3,
                                         uint32_t b0, uint32_t b1) {
    asm volatile("mma.sync.aligned.m16n8k8.row.col.f32.tf32.tf32.f32 "
                 "{%0,%1,%2,%3}, {%4,%5,%6,%7}, {%8,%9}, {%0,%1,%2,%3};"
                 : "+f"(d.x), "+f"(d.y), "+f"(d.z), "+f"(d.w)
                 : "r"(a0), "r"(a1), "r"(a2), "r"(a3), "r"(b0), "r"(b1));
}

__device__ __forceinline__ uint32_t smem_u32(const void* p) {
    uint32_t a;
    asm("{ .reg .u64 t; cvta.to.shared.u64 t, %1; cvt.u32.u64 %0, t; }"
        : "=r"(a) : "l"(p));
    return a;
}

__device__ __forceinline__ void cp_async16(uint32_t dst, const void* src, int nbytes) {
    asm volatile("cp.async.ca.shared.global [%0], [%1], 16, %2;"
                 :: "r"(dst), "l"(src), "r"(nbytes) : "memory");
}

// Issue cp.async for one chunk: X tile slice (32 cols x 128 rows) + B slice.
__device__ __forceinline__ void issue_chunk(uint32_t xs_addr, uint32_t bs_addr,
                                            const float* __restrict__ x,
                                            int row0, int cidx, int tid) {
    const int kc = cidx * CHUNK_COLS;
#pragma unroll
    for (int j = 0; j < 4; j++) {
        int i    = tid + j * GTHREADS;
        int r    = i >> 3;
        int seg  = i & 7;
        int grow = row0 + r;
        int gsrc = (grow < NN) ? grow : (NN - 1);
        const float* src = x + (size_t)gsrc * DIN + kc + seg * 4;
        uint32_t dst = xs_addr + (uint32_t)(r * (XS_STRIDE * 4) + seg * 16);
        cp_async16(dst, src, (grow < NN) ? 16 : 0);
    }
    {
        const char* bsrc = (const char*)(g_bfrag + (size_t)cidx * BCHUNK_U2) + tid * 16;
        cp_async16(bs_addr + tid * 16, bsrc, 16);
    }
    asm volatile("cp.async.commit_group;" ::: "memory");
}

// Precompute B fragments once (grid 16 x 256)
__global__ void bfrag_kernel(const float* __restrict__ w) {
    int i = blockIdx.x * 256 + threadIdx.x;
    if (i >= BFRAG_N) return;
    int ks  = i >> 7;
    int rem = i & 127;
    int nb  = rem >> 5;
    int ln  = rem & 31;
    int t = ln & 3, g = ln >> 2;
    float w0 = w[(ks * 8 + t)     * DOUT + nb * 8 + g];
    float w1 = w[(ks * 8 + t + 4) * DOUT + nb * 8 + g];
    g_bfrag[i] = make_uint2(f2tf32(w0), f2tf32(w1));
}

__global__ __launch_bounds__(GTHREADS, 4) void gemm_kernel(const float* __restrict__ x) {
    extern __shared__ char smem[];
    float* Xbuf = (float*)smem;
    uint2* Bbuf = (uint2*)(smem + 2 * XBUF_BYTES);
    const uint32_t xb_addr0 = smem_u32(Xbuf);
    const uint32_t xb_addr1 = xb_addr0 + XBUF_BYTES;
    const uint32_t bb_addr0 = smem_u32(Bbuf);
    const uint32_t bb_addr1 = bb_addr0 + BCHUNK_BYTES;

    const int tid  = threadIdx.x;
    const int row0 = blockIdx.x * RPB;

    issue_chunk(xb_addr0, bb_addr0, x, row0, 0, tid);
    issue_chunk(xb_addr1, bb_addr1, x, row0, 1, tid);

    const int wid  = tid >> 5;
    const int lane = tid & 31;
    const int t    = lane & 3;
    const int g    = lane >> 2;
    const int rl   = wid * RPW;

    float4 acc[4];
#pragma unroll
    for (int nb = 0; nb < 4; nb++) acc[nb] = make_float4(0.f, 0.f, 0.f, 0.f);

    const int offA = (rl + g) * XS_STRIDE + t;
    const int offB = (rl + g + 8) * XS_STRIDE + t;

#pragma unroll
    for (int c = 0; c < NCHUNK; c++) {
        if (c < NCHUNK - 1)
            asm volatile("cp.async.wait_group 1;" ::: "memory");
        else
            asm volatile("cp.async.wait_group 0;" ::: "memory");
        __syncthreads();

        const float* Xs = Xbuf + (c & 1) * XBUF_FLOATS;
        const uint2* Bs = Bbuf + (c & 1) * BCHUNK_U2;
#pragma unroll
        for (int ksl = 0; ksl < KSPC; ksl++) {
            const int k0 = ksl * 8;
            uint32_t a0 = f2tf32(Xs[offA + k0]);
            uint32_t a1 = f2tf32(Xs[offB + k0]);
            uint32_t a2 = f2tf32(Xs[offA + k0 + 4]);
            uint32_t a3 = f2tf32(Xs[offB + k0 + 4]);

            const uint2* bp = Bs + ksl * 4 * 32 + lane;
            uint2 b0 = bp[0 * 32];
            uint2 b1 = bp[1 * 32];
            uint2 b2 = bp[2 * 32];
            uint2 b3 = bp[3 * 32];
            mma_tf32(acc[0], a0, a1, a2, a3, b0.x, b0.y);
            mma_tf32(acc[1], a0, a1, a2, a3, b1.x, b1.y);
            mma_tf32(acc[2], a0, a1, a2, a3, b2.x, b2.y);
            mma_tf32(acc[3], a0, a1, a2, a3, b3.x, b3.y);
        }

        if (c + 2 < NCHUNK) {
            __syncthreads();
            issue_chunk((c & 1) ? xb_addr1 : xb_addr0,
                        (c & 1) ? bb_addr1 : bb_addr0,
                        x, row0, c + 2, tid);
        }
    }

    // Epilogue: proven float2 stores per (row, nb)
    const int r0 = row0 + rl + g;
    const int r1 = row0 + rl + g + 8;
#pragma unroll
    for (int nb = 0; nb < 4; nb++) {
        if (r0 < NN)
            *(float2*)(g_presup + (size_t)r0 * DOUT + nb * 8 + 2 * t) =
                make_float2(acc[nb].x, acc[nb].y);
        if (r1 < NN)
            *(float2*)(g_presup + (size_t)r1 * DOUT + nb * 8 + 2 * t) =
                make_float2(acc[nb].z, acc[nb].w);
    }
}

// ===========================================================================
// Scatter SpMM  g_accum[row[e]] += val[e] * pre_sup[col[e]]
// Proven Round-8/14 shape: 8 threads per edge (lane-level coalescing),
// one float4 gather + one red.global.add.v4.f32 per thread.
// ===========================================================================
__global__ __launch_bounds__(256) void scatter_kernel(const int*   __restrict__ arow,
                                                      const int*   __restrict__ acol,
                                                      const float* __restrict__ aval,
                                                      int n_edges) {
    long long gdx = (long long)blockIdx.x * blockDim.x + threadIdx.x;
    int e    = (int)(gdx >> 3);
    int part = (int)(gdx & 7);
    if (e >= n_edges) return;

    int   r = arow[e];
    int   c = acol[e];
    float v = aval[e];

    float4 p = *(const float4*)(g_presup + (size_t)c * DOUT + part * 4);
    float m0 = v * p.x, m1 = v * p.y, m2 = v * p.z, m3 = v * p.w;

    float* dst = g_accum + (size_t)r * DOUT + part * 4;
    asm volatile("red.global.add.v4.f32 [%0], {%1, %2, %3, %4};"
                 :: "l"(dst), "f"(m0), "f"(m1), "f"(m2), "f"(m3)
                 : "memory");
}

// ===========================================================================
// ReLU: out = relu(g_accum); g_accum = 0. Two independent float4 per thread
// (loads issued back-to-back -> MLP=2) before any store; only the last
// block's threads take predicates.
// ===========================================================================
__global__ __launch_bounds__(256) void relu_kernel(float* __restrict__ out, int n4) {
    int base = (blockIdx.x * 256 + threadIdx.x) * 2;
    const float4 z = make_float4(0.f, 0.f, 0.f, 0.f);
    if (base + 1 < n4) {
        float4 v0 = ((const float4*)g_accum)[base];
        float4 v1 = ((const float4*)g_accum)[base + 1];
        v0.x = fmaxf(v0.x, 0.f); v0.y = fmaxf(v0.y, 0.f);
        v0.z = fmaxf(v0.z, 0.f); v0.w = fmaxf(v0.w, 0.f);
        v1.x = fmaxf(v1.x, 0.f); v1.y = fmaxf(v1.y, 0.f);
        v1.z = fmaxf(v1.z, 0.f); v1.w = fmaxf(v1.w, 0.f);
        ((float4*)out)[base]     = v0;
        ((float4*)out)[base + 1] = v1;
        ((float4*)g_accum)[base]     = z;
        ((float4*)g_accum)[base + 1] = z;
    } else if (base < n4) {
        float4 v0 = ((const float4*)g_accum)[base];
        v0.x = fmaxf(v0.x, 0.f); v0.y = fmaxf(v0.y, 0.f);
        v0.z = fmaxf(v0.z, 0.f); v0.w = fmaxf(v0.w, 0.f);
        ((float4*)out)[base] = v0;
        ((float4*)g_accum)[base] = z;
    }
}

// ===========================================================================
// kernel_launch: bfrag -> gemm -> scatter -> relu
// ===========================================================================
extern "C" void kernel_launch(void* const* d_in, const int* in_sizes, int n_in,
                              void* d_out, int out_size) {
    const float* x    = (const float*)d_in[0];
    const int*   arow = (const int*)  d_in[1];
    const int*   acol = (const int*)  d_in[2];
    const float* aval = (const float*)d_in[3];
    const float* w    = (const float*)d_in[4];
    float*       out  = (float*)d_out;

    const int n_edges = in_sizes[1];

    cudaFuncSetAttribute(gemm_kernel, cudaFuncAttributeMaxDynamicSharedMemorySize,
                         SMEM_BYTES);

    bfrag_kernel<<<(BFRAG_N + 255) / 256, 256>>>(w);

    gemm_kernel<<<(NN + RPB - 1) / RPB, GTHREADS, SMEM_BYTES>>>(x);

    long long sthreads = (long long)n_edges * 8;
    int sblocks = (int)((sthreads + 255) / 256);
    scatter_kernel<<<sblocks, 256>>>(arow, acol, aval, n_edges);

    int n4 = out_size / 4;
    int rthreads = (n4 + 1) / 2;
    relu_kernel<<<(rthreads + 255) / 256, 256>>>(out, n4);
}